// round 14
// baseline (speedup 1.0000x reference)
#include <cuda_runtime.h>
#include <cuda_bf16.h>
#include <math.h>

// Problem shape (fixed by dataset): T=512, N=512, C=80, S=128, L=257
#define CC 80
#define SS 128
#define NEGV  (-1e30f)
#define LOG2E 1.4426950408889634f
#define LN2   0.6931471805599453f
#define NT    256                // 8 warps; thread tid owns lattice cell tid+1

__device__ __forceinline__ float ex2f(float x) {
    float r; asm("ex2.approx.ftz.f32 %0, %1;" : "=f"(r) : "f"(x)); return r;
}
__device__ __forceinline__ float lg2f(float x) {
    float r; asm("lg2.approx.f32 %0, %1;" : "=f"(r) : "f"(x)); return r;
}
// sorted 3-way log2-sum-exp2: 2 ex2 + 1 lg2 (NEG inputs give exact 0 terms)
__device__ __forceinline__ float lse3(float x, float y, float z) {
    float hi  = fmaxf(x, y), lo1 = fminf(x, y);
    float m   = fmaxf(hi, z);
    float mid = fmaxf(lo1, fminf(hi, z));
    float lo  = fminf(lo1, z);
    return m + lg2f(1.0f + ex2f(mid - m) + ex2f(lo - m));
}

// One block (256 threads, 8 warps) per sequence; one lattice cell per thread
// in a register (cell 0 = scalar on warp 0). Uniform branchless LSE for label
// AND blank cells. One __syncthreads per step; neighbors via 2 shfl_up; warp
// boundary via parity-double-buffered smem pair.
__global__ __launch_bounds__(NT)
void ctc_loss_kernel(const float* __restrict__ log_probs,     // (T, N, C)
                     const int*   __restrict__ targets,       // (N, S)
                     const int*   __restrict__ input_lengths, // (N,)
                     const int*   __restrict__ target_lengths,// (N,)
                     float*       __restrict__ out,           // (N,)
                     int N)
{
    __shared__ float bnd[2][8][2];   // [parity][warp][{lane30,lane31}] alphas
    __shared__ float fin[260];       // epilogue gather

    const int tid  = threadIdx.x;
    const int lane = tid & 31;
    const int w    = tid >> 5;
    const int n    = blockIdx.x;
    const int len  = input_lengths[n];      // in [256, 512]

    // my cell s = tid+1; odd s (tid even) = label cell, even s = blank
    const bool isLab = (tid & 1) == 0;
    int  c    = 0;
    bool skip = false;
    if (isLab) {
        const int j = tid >> 1;             // label index of cell s=2j+1
        c = targets[n * SS + j];
        if (j > 0) skip = (c != targets[n * SS + j - 1]);
    }

    const size_t tstride = (size_t)N * CC;
    const float* lp = log_probs + (size_t)n * CC;

    // ---- t = 0 (log2 domain) ----
    float alpha0 = __ldg(lp) * LOG2E;                        // cell 0 (warp0 uniform)
    float a = (tid == 0) ? __ldg(lp + c) * LOG2E : NEGV;     // cell tid+1

    if (lane >= 30) bnd[0][w][lane - 30] = a;

    // emission pipeline: pc = raw log-prob for step t (starts at t=1)
    const float* ptr = lp + tstride + c;
    float pc = __ldg(ptr);
    ptr += tstride;                          // next prefetch address (t=2)
    __syncthreads();

    // ---- main loop t = 1 .. len-2 (final step peeled; len>=256) ----
    for (int t = 1; t <= len - 2; ++t) {
        float q = __ldg(ptr);                // emission for t+1 (always valid)
        ptr += tstride;

        const int p = (t - 1) & 1;
        float s1 = __shfl_up_sync(0xffffffffu, a, 1);   // cell s-1
        float s2 = __shfl_up_sync(0xffffffffu, a, 2);   // cell s-2
        if (lane == 0) {
            s1 = (w == 0) ? alpha0 : bnd[p][w - 1][1];
            s2 = (w == 0) ? NEGV   : bnd[p][w - 1][0];
        } else if (lane == 1) {
            s2 = (w == 0) ? alpha0 : bnd[p][w - 1][1];
        }

        float nv = fmaf(pc, LOG2E, lse3(a, s1, skip ? s2 : NEGV));
        if (w == 0) {                        // cell 0 blank self-loop (uniform)
            float eb = __shfl_sync(0xffffffffu, pc, 1);  // lane1 = blank class
            alpha0 = fmaf(eb, LOG2E, alpha0);
        }
        a = nv;
        if (lane >= 30) bnd[t & 1][w][lane - 30] = a;
        pc = q;
        __syncthreads();
    }

    // ---- final step t = len-1 (no prefetch, no publish) ----
    {
        const int t = len - 1;
        const int p = (t - 1) & 1;
        float s1 = __shfl_up_sync(0xffffffffu, a, 1);
        float s2 = __shfl_up_sync(0xffffffffu, a, 2);
        if (lane == 0) {
            s1 = (w == 0) ? alpha0 : bnd[p][w - 1][1];
            s2 = (w == 0) ? NEGV   : bnd[p][w - 1][0];
        } else if (lane == 1) {
            s2 = (w == 0) ? alpha0 : bnd[p][w - 1][1];
        }
        a = fmaf(pc, LOG2E, lse3(a, s1, skip ? s2 : NEGV));
        if (w == 0) {
            float eb = __shfl_sync(0xffffffffu, pc, 1);
            alpha0 = fmaf(eb, LOG2E, alpha0);
        }
    }

    // ---- epilogue: gather, combine cells 2*tl and 2*tl-1 ----
    fin[tid + 1] = a;
    if (tid == 0) fin[0] = alpha0;
    __syncthreads();

    if (tid == 0) {
        const int tl = target_lengths[n];
        float v1 = fin[2 * tl];
        float v2 = fin[2 * tl - 1];
        float m  = fmaxf(v1, v2);
        float loss = -(m + lg2f(ex2f(v1 - m) + ex2f(v2 - m))) * LN2;
        if (!isfinite(loss) || loss >= 1e10f) loss = 0.0f;
        out[n] = loss;
    }
}

extern "C" void kernel_launch(void* const* d_in, const int* in_sizes, int n_in,
                              void* d_out, int out_size)
{
    const float* log_probs      = (const float*)d_in[0];
    const int*   targets        = (const int*)  d_in[1];
    const int*   input_lengths  = (const int*)  d_in[2];
    const int*   target_lengths = (const int*)  d_in[3];
    float*       out            = (float*)d_out;

    const int N = in_sizes[2];   // batch from input_lengths element count

    ctc_loss_kernel<<<N, NT>>>(log_probs, targets, input_lengths,
                               target_lengths, out, N);
}